// round 1
// baseline (speedup 1.0000x reference)
#include <cuda_runtime.h>
#include <cuda_bf16.h>
#include <cstdint>

// SparseBMM: y[b,m,n] = sum_k (A_masked[b,m,k]) * B[b,k,n]
// A_masked zeroes 64x64 tiles of A whose max-abs <= 1e-6.
// Shapes: A,B,C = [8, 2048, 2048] fp32.

#define BATCH 8
#define MDIM 2048
#define NDIM 2048
#define KDIM 2048
#define TILE 64
#define NTILES (MDIM / TILE)   // 32

// Block tile
#define BM 128
#define BN 128
#define BK 16
#define TM 8
#define TN 8
// threads = (BM/TM)*(BN/TN) = 256

__device__ unsigned char g_mask[BATCH * NTILES * NTILES];  // [b][mtile][ktile]

// ---------------------------------------------------------------------------
// Prescan: one block per 64x64 tile of A. 256 threads, 16 elems each.
// ---------------------------------------------------------------------------
__global__ void prescan_kernel(const float* __restrict__ A) {
    const int kt = blockIdx.x;   // ktile 0..31
    const int mt = blockIdx.y;   // mtile 0..31
    const int b  = blockIdx.z;   // batch 0..7

    const float* base = A + ((size_t)b * MDIM + (size_t)mt * TILE) * KDIM + (size_t)kt * TILE;
    const int tid = threadIdx.x;
    const int row = tid >> 2;        // 0..63
    const int c   = tid & 3;         // 0..3

    float mx = 0.0f;
#pragma unroll
    for (int j = 0; j < 4; j++) {
        float4 v = *(const float4*)(base + (size_t)row * KDIM + (c + j * 4) * 4);
        mx = fmaxf(mx, fmaxf(fmaxf(fabsf(v.x), fabsf(v.y)),
                             fmaxf(fabsf(v.z), fabsf(v.w))));
    }
#pragma unroll
    for (int o = 16; o; o >>= 1)
        mx = fmaxf(mx, __shfl_xor_sync(0xffffffffu, mx, o));

    __shared__ float wmax[8];
    if ((tid & 31) == 0) wmax[tid >> 5] = mx;
    __syncthreads();
    if (tid == 0) {
        float m = wmax[0];
#pragma unroll
        for (int i = 1; i < 8; i++) m = fmaxf(m, wmax[i]);
        g_mask[(b << 10) + (mt << 5) + kt] = (m > 1e-6f) ? (unsigned char)1 : (unsigned char)0;
    }
}

// ---------------------------------------------------------------------------
// SIMT fp32 GEMM: 128x128 block tile, BK=16, 8x8 per thread, 256 threads.
// A staged transposed in smem (pad +4 floats: float4-aligned, low-conflict).
// ---------------------------------------------------------------------------
__global__ __launch_bounds__(256, 2) void gemm_kernel(const float* __restrict__ A,
                                                      const float* __restrict__ Bm,
                                                      float* __restrict__ C) {
    __shared__ float As[BK][BM + 4];   // transposed: As[k][m]
    __shared__ float Bs[BK][BN];

    const int b  = blockIdx.z;
    const int bm = blockIdx.y * BM;
    const int bn = blockIdx.x * BN;

    const float* Ab = A  + (size_t)b * MDIM * KDIM;
    const float* Bb = Bm + (size_t)b * KDIM * NDIM;
    float*       Cb = C  + (size_t)b * MDIM * NDIM;

    const int tid = threadIdx.x;
    const int tr = (tid >> 4) * TM;   // 0,8,...,120
    const int tc = (tid & 15) * TN;   // 0,8,...,120

    // A global-load geometry: 128 rows x 4 float4-cols; 512 float4, 2/thread.
    // i=0 -> rows 0..63, i=1 -> rows 64..127 (mtile differs per i).
    const int a_row = tid >> 2;       // 0..63 (i adds 64)
    const int a_c4  = tid & 3;        // 0..3
    // B global-load geometry: 16 rows x 32 float4-cols; 512 float4, 2/thread.
    const int b_row = tid >> 5;       // 0..7 (i adds 8)
    const int b_c4  = tid & 31;       // 0..31

    const int mtile0 = (bm >> 6);               // rows 0..63 of this block
    const int mtile1 = mtile0 + 1;              // rows 64..127
    const int mask_base = (b << 10);

    float acc[TM][TN];
#pragma unroll
    for (int i = 0; i < TM; i++)
#pragma unroll
        for (int j = 0; j < TN; j++) acc[i][j] = 0.0f;

    for (int kt = 0; kt < KDIM; kt += BK) {
        const int ktile = kt >> 6;
        const float s0 = g_mask[mask_base + (mtile0 << 5) + ktile] ? 1.0f : 0.0f;
        const float s1 = g_mask[mask_base + (mtile1 << 5) + ktile] ? 1.0f : 0.0f;

        // Load + transpose A tile (apply tile mask)
#pragma unroll
        for (int i = 0; i < 2; i++) {
            const int row = a_row + i * 64;
            const float s = (i == 0) ? s0 : s1;
            float4 v = *(const float4*)(Ab + (size_t)(bm + row) * KDIM + kt + a_c4 * 4);
            As[a_c4 * 4 + 0][row] = v.x * s;
            As[a_c4 * 4 + 1][row] = v.y * s;
            As[a_c4 * 4 + 2][row] = v.z * s;
            As[a_c4 * 4 + 3][row] = v.w * s;
        }
        // Load B tile
#pragma unroll
        for (int i = 0; i < 2; i++) {
            const int row = b_row + i * 8;
            float4 v = *(const float4*)(Bb + (size_t)(kt + row) * NDIM + bn + b_c4 * 4);
            *(float4*)&Bs[row][b_c4 * 4] = v;
        }
        __syncthreads();

#pragma unroll
        for (int k = 0; k < BK; k++) {
            float ra[TM], rb[TN];
            *(float4*)&ra[0] = *(const float4*)&As[k][tr];
            *(float4*)&ra[4] = *(const float4*)&As[k][tr + 4];
            *(float4*)&rb[0] = *(const float4*)&Bs[k][tc];
            *(float4*)&rb[4] = *(const float4*)&Bs[k][tc + 4];
#pragma unroll
            for (int i = 0; i < TM; i++)
#pragma unroll
                for (int j = 0; j < TN; j++)
                    acc[i][j] = fmaf(ra[i], rb[j], acc[i][j]);
        }
        __syncthreads();
    }

    // Epilogue: float4 stores
#pragma unroll
    for (int i = 0; i < TM; i++) {
        float* crow = Cb + (size_t)(bm + tr + i) * NDIM + bn + tc;
#pragma unroll
        for (int j = 0; j < TN; j += 4) {
            float4 v = make_float4(acc[i][j], acc[i][j + 1], acc[i][j + 2], acc[i][j + 3]);
            *(float4*)(crow + j) = v;
        }
    }
}

extern "C" void kernel_launch(void* const* d_in, const int* in_sizes, int n_in,
                              void* d_out, int out_size) {
    const float* a = (const float*)d_in[0];
    const float* b = (const float*)d_in[1];
    float* out = (float*)d_out;

    dim3 pre_grid(NTILES, NTILES, BATCH);
    prescan_kernel<<<pre_grid, 256>>>(a);

    dim3 gemm_grid(NDIM / BN, MDIM / BM, BATCH);
    gemm_kernel<<<gemm_grid, 256>>>(a, b, out);
}

// round 4
// speedup vs baseline: 2.5997x; 2.5997x over previous
#include <cuda_runtime.h>
#include <cuda_bf16.h>
#include <cstdint>

// SparseBMM: y[b,m,n] = sum_k A_masked[b,m,k] * B[b,k,n], fp32 [8,2048,2048].
// A_masked zeroes 64x64 tiles of A whose max-abs <= 1e-6.
//
// Harness PTX target is compute_103 (no 'a') -> tcgen05 unavailable.
// Path: bf16 mma.sync (m16n8k16) with 2-term hi/lo split (3 products),
// fp32 accumulate. Expected rel_err ~1e-5 vs tolerance 1e-3.

#define BATCH 8
#define MDIM 2048
#define NDIM 2048
#define KDIM 2048
#define NTILES 32

#define BM 128
#define BN 128
#define BK 32
#define STAGES 4
#define NK (KDIM / BK)          // 64

#define A_ST_BYTES 8192         // 128 rows x 32 bf16 = 128x64B
#define B_ST_BYTES 8192         // 32 rows x 128 bf16 = 32x256B
#define STAGE_BYTES (2 * A_ST_BYTES + 2 * B_ST_BYTES)   // 32768
#define SMEM_TOTAL (STAGES * STAGE_BYTES)               // 131072

__device__ unsigned char g_mask[BATCH * NTILES * NTILES];
__device__ __nv_bfloat16 g_Ah[(size_t)BATCH * MDIM * KDIM];
__device__ __nv_bfloat16 g_Al[(size_t)BATCH * MDIM * KDIM];
__device__ __nv_bfloat16 g_Bh[(size_t)BATCH * KDIM * NDIM];
__device__ __nv_bfloat16 g_Bl[(size_t)BATCH * KDIM * NDIM];

// ---------------- helpers ----------------
__device__ __forceinline__ uint32_t smem_u32(const void* p) {
    uint32_t a;
    asm("{ .reg .u64 t; cvta.to.shared.u64 t, %1; cvt.u32.u64 %0, t; }" : "=r"(a) : "l"(p));
    return a;
}
__device__ __forceinline__ void cpa16(uint32_t dst, const void* src) {
    asm volatile("cp.async.cg.shared.global [%0], [%1], 16;" :: "r"(dst), "l"(src));
}
__device__ __forceinline__ void ldsm_x4(uint32_t* r, uint32_t addr) {
    asm volatile("ldmatrix.sync.aligned.m8n8.x4.shared.b16 {%0,%1,%2,%3}, [%4];"
                 : "=r"(r[0]), "=r"(r[1]), "=r"(r[2]), "=r"(r[3]) : "r"(addr));
}
__device__ __forceinline__ void ldsm_x4_t(uint32_t* r, uint32_t addr) {
    asm volatile("ldmatrix.sync.aligned.m8n8.x4.trans.shared.b16 {%0,%1,%2,%3}, [%4];"
                 : "=r"(r[0]), "=r"(r[1]), "=r"(r[2]), "=r"(r[3]) : "r"(addr));
}
__device__ __forceinline__ void mma_bf16(float* d, const uint32_t* a, const uint32_t* b) {
    asm volatile(
        "mma.sync.aligned.m16n8k16.row.col.f32.bf16.bf16.f32 "
        "{%0,%1,%2,%3}, {%4,%5,%6,%7}, {%8,%9}, {%0,%1,%2,%3};"
        : "+f"(d[0]), "+f"(d[1]), "+f"(d[2]), "+f"(d[3])
        : "r"(a[0]), "r"(a[1]), "r"(a[2]), "r"(a[3]), "r"(b[0]), "r"(b[1]));
}
__device__ __forceinline__ uint32_t pack_bf(__nv_bfloat16 x, __nv_bfloat16 y) {
    return ((uint32_t)__bfloat16_as_ushort(y) << 16) | (uint32_t)__bfloat16_as_ushort(x);
}

// ---------------------------------------------------------------------------
// Prescan: one block per 64x64 tile of A.
// ---------------------------------------------------------------------------
__global__ void prescan_kernel(const float* __restrict__ A) {
    const int kt = blockIdx.x, mt = blockIdx.y, b = blockIdx.z;
    const float* base = A + ((size_t)b * MDIM + (size_t)mt * 64) * KDIM + (size_t)kt * 64;
    const int tid = threadIdx.x;
    const int row = tid >> 2, c = tid & 3;
    float mx = 0.0f;
#pragma unroll
    for (int j = 0; j < 4; j++) {
        float4 v = *(const float4*)(base + (size_t)row * KDIM + (c + j * 4) * 4);
        mx = fmaxf(mx, fmaxf(fmaxf(fabsf(v.x), fabsf(v.y)), fmaxf(fabsf(v.z), fabsf(v.w))));
    }
#pragma unroll
    for (int o = 16; o; o >>= 1) mx = fmaxf(mx, __shfl_xor_sync(0xffffffffu, mx, o));
    __shared__ float wmax[8];
    if ((tid & 31) == 0) wmax[tid >> 5] = mx;
    __syncthreads();
    if (tid == 0) {
        float m = wmax[0];
#pragma unroll
        for (int i = 1; i < 8; i++) m = fmaxf(m, wmax[i]);
        g_mask[(b << 10) + (mt << 5) + kt] = (m > 1e-6f) ? 1 : 0;
    }
}

// ---------------------------------------------------------------------------
// Convert fp32 -> bf16 hi/lo. A applies the tile mask; B does not.
// One thread per float4 (grid covers 8*2048*2048/4 groups).
// ---------------------------------------------------------------------------
template <bool MASKED>
__global__ void conv_kernel(const float* __restrict__ X,
                            __nv_bfloat16* __restrict__ Xh,
                            __nv_bfloat16* __restrict__ Xl) {
    const size_t i4 = (size_t)blockIdx.x * blockDim.x + threadIdx.x;
    float4 v = ((const float4*)X)[i4];
    if (MASKED) {
        const size_t e0 = i4 * 4;
        const int b = (int)(e0 >> 22);
        const int row = (int)((e0 >> 11) & 2047);
        const int k = (int)(e0 & 2047);
        const float s = g_mask[(b << 10) + ((row >> 6) << 5) + (k >> 6)] ? 1.0f : 0.0f;
        v.x *= s; v.y *= s; v.z *= s; v.w *= s;
    }
    __nv_bfloat16 h0 = __float2bfloat16_rn(v.x);
    __nv_bfloat16 h1 = __float2bfloat16_rn(v.y);
    __nv_bfloat16 h2 = __float2bfloat16_rn(v.z);
    __nv_bfloat16 h3 = __float2bfloat16_rn(v.w);
    __nv_bfloat16 l0 = __float2bfloat16_rn(v.x - __bfloat162float(h0));
    __nv_bfloat16 l1 = __float2bfloat16_rn(v.y - __bfloat162float(h1));
    __nv_bfloat16 l2 = __float2bfloat16_rn(v.z - __bfloat162float(h2));
    __nv_bfloat16 l3 = __float2bfloat16_rn(v.w - __bfloat162float(h3));
    ((uint2*)Xh)[i4] = make_uint2(pack_bf(h0, h1), pack_bf(h2, h3));
    ((uint2*)Xl)[i4] = make_uint2(pack_bf(l0, l1), pack_bf(l2, l3));
}

// ---------------------------------------------------------------------------
// GEMM: bf16 mma.sync, 3 products (hh, hl, lh), 4-stage cp.async pipeline.
// 256 threads = 8 warps as 2(M) x 4(N); warp tile 64x32.
// ---------------------------------------------------------------------------
__global__ __launch_bounds__(256, 1) void gemm_mma(float* __restrict__ C) {
    extern __shared__ char smem[];
    const uint32_t sb = smem_u32(smem);
    const int tid = threadIdx.x;
    const int wid = tid >> 5, lane = tid & 31;
    const int b = blockIdx.z;
    const int bm = blockIdx.y * BM, bn = blockIdx.x * BN;

    const size_t boffA = (size_t)b * MDIM * KDIM;
    const size_t boffB = (size_t)b * KDIM * NDIM;
    const __nv_bfloat16* pAh = g_Ah + boffA;
    const __nv_bfloat16* pAl = g_Al + boffA;
    const __nv_bfloat16* pBh = g_Bh + boffB;
    const __nv_bfloat16* pBl = g_Bl + boffB;

    // cp.async geometry
    const int ar = tid >> 2, ac = tid & 3;       // A: rows ar, ar+64; 16B chunk ac
    const int bk = tid >> 3, bc = tid & 7;       // B: row bk; chunks bc, bc+8
    const uint32_t saw = (uint32_t)(ar * 4 + (ac ^ ((ar >> 1) & 3))) * 16;  // +4096 for row+64
    const uint32_t sbw = (uint32_t)(bk * 16 + (bc ^ (bk & 7))) * 16;        // +128 for chunk+8

    const __nv_bfloat16* gAh0 = pAh + (size_t)(bm + ar) * KDIM + ac * 8;
    const __nv_bfloat16* gAl0 = pAl + (size_t)(bm + ar) * KDIM + ac * 8;
    const __nv_bfloat16* gBh0 = pBh + (size_t)bk * NDIM + bn + bc * 8;
    const __nv_bfloat16* gBl0 = pBl + (size_t)bk * NDIM + bn + bc * 8;

    auto load_stage = [&](int t) {
        const uint32_t st = sb + (uint32_t)(t % STAGES) * STAGE_BYTES;
        const int koff = t * BK;                        // element offset in K
        const size_t aoff = (size_t)koff;
        const size_t boff = (size_t)koff * NDIM;
        cpa16(st + saw,                 gAh0 + aoff);
        cpa16(st + saw + 4096,          gAh0 + aoff + (size_t)64 * KDIM);
        cpa16(st + A_ST_BYTES + saw,        gAl0 + aoff);
        cpa16(st + A_ST_BYTES + saw + 4096, gAl0 + aoff + (size_t)64 * KDIM);
        const uint32_t sB = st + 2 * A_ST_BYTES;
        cpa16(sB + sbw,                     gBh0 + boff);
        cpa16(sB + sbw + 128,               gBh0 + boff + 64);
        cpa16(sB + B_ST_BYTES + sbw,        gBl0 + boff);
        cpa16(sB + B_ST_BYTES + sbw + 128,  gBl0 + boff + 64);
    };

    // warp tiling
    const int wm = (wid >> 2) * 64;      // 0 or 64
    const int wn = (wid & 3) * 32;       // 0,32,64,96

    // ldmatrix lane geometry
    const int a_r = wm + (lane & 15);            // + i*16
    const int a_cL = (lane >> 4);                // + ks*2
    const int b_k = (lane & 15);                 // + ks*16
    const int b_cL = (wn >> 3) + (lane >> 4);    // + j2*2

    float acc[4][4][4];
#pragma unroll
    for (int i = 0; i < 4; i++)
#pragma unroll
        for (int j = 0; j < 4; j++)
#pragma unroll
            for (int q = 0; q < 4; q++) acc[i][j][q] = 0.0f;

    // prologue
#pragma unroll
    for (int t = 0; t < STAGES - 1; ++t) {
        load_stage(t);
        asm volatile("cp.async.commit_group;" ::: "memory");
    }

    for (int t = 0; t < NK; ++t) {
        asm volatile("cp.async.wait_group %0;" :: "n"(STAGES - 2) : "memory");
        __syncthreads();

        if (t + STAGES - 1 < NK) load_stage(t + STAGES - 1);
        asm volatile("cp.async.commit_group;" ::: "memory");

        const uint32_t st = sb + (uint32_t)(t % STAGES) * STAGE_BYTES;
        const uint32_t sAh = st;
        const uint32_t sAl = st + A_ST_BYTES;
        const uint32_t sBh = st + 2 * A_ST_BYTES;
        const uint32_t sBl = sBh + B_ST_BYTES;

#pragma unroll
        for (int ks = 0; ks < 2; ks++) {
            uint32_t ah[4][4], al[4][4], bh[2][4], bl[2][4];
#pragma unroll
            for (int i = 0; i < 4; i++) {
                const int r = a_r + i * 16;
                const int c = ks * 2 + a_cL;
                const uint32_t off = (uint32_t)(r * 4 + (c ^ ((r >> 1) & 3))) * 16;
                ldsm_x4(ah[i], sAh + off);
                ldsm_x4(al[i], sAl + off);
            }
#pragma unroll
            for (int j2 = 0; j2 < 2; j2++) {
                const int k = ks * 16 + b_k;
                const int c = b_cL + j2 * 2;
                const uint32_t off = (uint32_t)(k * 16 + (c ^ (k & 7))) * 16;
                ldsm_x4_t(bh[j2], sBh + off);
                ldsm_x4_t(bl[j2], sBl + off);
            }
#pragma unroll
            for (int i = 0; i < 4; i++)
#pragma unroll
                for (int j2 = 0; j2 < 2; j2++)
#pragma unroll
                    for (int n8 = 0; n8 < 2; n8++) {
                        float* a4 = acc[i][j2 * 2 + n8];
                        mma_bf16(a4, ah[i], &bh[j2][n8 * 2]);
                        mma_bf16(a4, ah[i], &bl[j2][n8 * 2]);
                        mma_bf16(a4, al[i], &bh[j2][n8 * 2]);
                    }
        }
        __syncthreads();
    }

    // epilogue
    float* Cb = C + (size_t)b * MDIM * NDIM;
    const int r0 = bm + wm + (lane >> 2);
    const int c0 = bn + wn + (lane & 3) * 2;
#pragma unroll
    for (int i = 0; i < 4; i++) {
#pragma unroll
        for (int j = 0; j < 4; j++) {
            const int row = r0 + i * 16;
            const int col = c0 + j * 8;
            *(float2*)&Cb[(size_t)row * NDIM + col] = make_float2(acc[i][j][0], acc[i][j][1]);
            *(float2*)&Cb[(size_t)(row + 8) * NDIM + col] = make_float2(acc[i][j][2], acc[i][j][3]);
        }
    }
}

extern "C" void kernel_launch(void* const* d_in, const int* in_sizes, int n_in,
                              void* d_out, int out_size) {
    const float* a = (const float*)d_in[0];
    const float* b = (const float*)d_in[1];
    float* out = (float*)d_out;

    __nv_bfloat16 *Ah, *Al, *Bh, *Bl;
    cudaGetSymbolAddress((void**)&Ah, g_Ah);
    cudaGetSymbolAddress((void**)&Al, g_Al);
    cudaGetSymbolAddress((void**)&Bh, g_Bh);
    cudaGetSymbolAddress((void**)&Bl, g_Bl);

    dim3 pre_grid(NTILES, NTILES, BATCH);
    prescan_kernel<<<pre_grid, 256>>>(a);

    const int conv_blocks = (BATCH * MDIM * KDIM / 4) / 256;   // 32768
    conv_kernel<true><<<conv_blocks, 256>>>(a, Ah, Al);
    conv_kernel<false><<<conv_blocks, 256>>>(b, Bh, Bl);

    cudaFuncSetAttribute(gemm_mma, cudaFuncAttributeMaxDynamicSharedMemorySize, SMEM_TOTAL);
    dim3 grid(NDIM / BN, MDIM / BM, BATCH);
    gemm_mma<<<grid, 256, SMEM_TOTAL>>>(out);
}

// round 5
// speedup vs baseline: 2.9316x; 1.1277x over previous
#include <cuda_runtime.h>
#include <cuda_bf16.h>
#include <cstdint>

// SparseBMM: y[b,m,n] = sum_k A_masked[b,m,k] * B[b,k,n], fp32 [8,2048,2048].
// A_masked zeroes 64x64 tiles of A whose max-abs <= 1e-6.
// bf16 mma.sync m16n8k16, 2-term hi/lo split (3 products), fp32 accumulate.
// R5: 512-thread CTA (BM=256), 16 warps, single barrier per k-iter.

#define BATCH 8
#define MDIM 2048
#define NDIM 2048
#define KDIM 2048
#define NTILES 32

#define BM 256
#define BN 128
#define BK 32
#define STAGES 4
#define NK (KDIM / BK)          // 64

#define A_ST_BYTES 16384        // 256 rows x 32 bf16 = 256x64B
#define B_ST_BYTES 8192         // 32 rows x 128 bf16 = 32x256B
#define STAGE_BYTES (2 * A_ST_BYTES + 2 * B_ST_BYTES)   // 49152
#define SMEM_TOTAL (STAGES * STAGE_BYTES)               // 196608

__device__ unsigned char g_mask[BATCH * NTILES * NTILES];
__device__ __nv_bfloat16 g_Ah[(size_t)BATCH * MDIM * KDIM];
__device__ __nv_bfloat16 g_Al[(size_t)BATCH * MDIM * KDIM];
__device__ __nv_bfloat16 g_Bh[(size_t)BATCH * KDIM * NDIM];
__device__ __nv_bfloat16 g_Bl[(size_t)BATCH * KDIM * NDIM];

// ---------------- helpers ----------------
__device__ __forceinline__ uint32_t smem_u32(const void* p) {
    uint32_t a;
    asm("{ .reg .u64 t; cvta.to.shared.u64 t, %1; cvt.u32.u64 %0, t; }" : "=r"(a) : "l"(p));
    return a;
}
__device__ __forceinline__ void cpa16(uint32_t dst, const void* src) {
    asm volatile("cp.async.cg.shared.global [%0], [%1], 16;" :: "r"(dst), "l"(src));
}
__device__ __forceinline__ void ldsm_x4(uint32_t* r, uint32_t addr) {
    asm volatile("ldmatrix.sync.aligned.m8n8.x4.shared.b16 {%0,%1,%2,%3}, [%4];"
                 : "=r"(r[0]), "=r"(r[1]), "=r"(r[2]), "=r"(r[3]) : "r"(addr));
}
__device__ __forceinline__ void ldsm_x4_t(uint32_t* r, uint32_t addr) {
    asm volatile("ldmatrix.sync.aligned.m8n8.x4.trans.shared.b16 {%0,%1,%2,%3}, [%4];"
                 : "=r"(r[0]), "=r"(r[1]), "=r"(r[2]), "=r"(r[3]) : "r"(addr));
}
__device__ __forceinline__ void mma_bf16(float* d, const uint32_t* a, const uint32_t* b) {
    asm volatile(
        "mma.sync.aligned.m16n8k16.row.col.f32.bf16.bf16.f32 "
        "{%0,%1,%2,%3}, {%4,%5,%6,%7}, {%8,%9}, {%0,%1,%2,%3};"
        : "+f"(d[0]), "+f"(d[1]), "+f"(d[2]), "+f"(d[3])
        : "r"(a[0]), "r"(a[1]), "r"(a[2]), "r"(a[3]), "r"(b[0]), "r"(b[1]));
}
__device__ __forceinline__ uint32_t pack_bf(__nv_bfloat16 x, __nv_bfloat16 y) {
    return ((uint32_t)__bfloat16_as_ushort(y) << 16) | (uint32_t)__bfloat16_as_ushort(x);
}

// ---------------------------------------------------------------------------
// Prescan: one block per 64x64 tile of A.
// ---------------------------------------------------------------------------
__global__ void prescan_kernel(const float* __restrict__ A) {
    const int kt = blockIdx.x, mt = blockIdx.y, b = blockIdx.z;
    const float* base = A + ((size_t)b * MDIM + (size_t)mt * 64) * KDIM + (size_t)kt * 64;
    const int tid = threadIdx.x;
    const int row = tid >> 2, c = tid & 3;
    float mx = 0.0f;
#pragma unroll
    for (int j = 0; j < 4; j++) {
        float4 v = *(const float4*)(base + (size_t)row * KDIM + (c + j * 4) * 4);
        mx = fmaxf(mx, fmaxf(fmaxf(fabsf(v.x), fabsf(v.y)), fmaxf(fabsf(v.z), fabsf(v.w))));
    }
#pragma unroll
    for (int o = 16; o; o >>= 1) mx = fmaxf(mx, __shfl_xor_sync(0xffffffffu, mx, o));
    __shared__ float wmax[8];
    if ((tid & 31) == 0) wmax[tid >> 5] = mx;
    __syncthreads();
    if (tid == 0) {
        float m = wmax[0];
#pragma unroll
        for (int i = 1; i < 8; i++) m = fmaxf(m, wmax[i]);
        g_mask[(b << 10) + (mt << 5) + kt] = (m > 1e-6f) ? 1 : 0;
    }
}

// ---------------------------------------------------------------------------
// Convert fp32 -> bf16 hi/lo. A applies the tile mask; B does not.
// ---------------------------------------------------------------------------
template <bool MASKED>
__global__ void conv_kernel(const float* __restrict__ X,
                            __nv_bfloat16* __restrict__ Xh,
                            __nv_bfloat16* __restrict__ Xl) {
    const size_t i4 = (size_t)blockIdx.x * blockDim.x + threadIdx.x;
    float4 v = ((const float4*)X)[i4];
    if (MASKED) {
        const size_t e0 = i4 * 4;
        const int b = (int)(e0 >> 22);
        const int row = (int)((e0 >> 11) & 2047);
        const int k = (int)(e0 & 2047);
        const float s = g_mask[(b << 10) + ((row >> 6) << 5) + (k >> 6)] ? 1.0f : 0.0f;
        v.x *= s; v.y *= s; v.z *= s; v.w *= s;
    }
    __nv_bfloat16 h0 = __float2bfloat16_rn(v.x);
    __nv_bfloat16 h1 = __float2bfloat16_rn(v.y);
    __nv_bfloat16 h2 = __float2bfloat16_rn(v.z);
    __nv_bfloat16 h3 = __float2bfloat16_rn(v.w);
    __nv_bfloat16 l0 = __float2bfloat16_rn(v.x - __bfloat162float(h0));
    __nv_bfloat16 l1 = __float2bfloat16_rn(v.y - __bfloat162float(h1));
    __nv_bfloat16 l2 = __float2bfloat16_rn(v.z - __bfloat162float(h2));
    __nv_bfloat16 l3 = __float2bfloat16_rn(v.w - __bfloat162float(h3));
    ((uint2*)Xh)[i4] = make_uint2(pack_bf(h0, h1), pack_bf(h2, h3));
    ((uint2*)Xl)[i4] = make_uint2(pack_bf(l0, l1), pack_bf(l2, l3));
}

// ---------------------------------------------------------------------------
// GEMM: bf16 mma.sync, 3 products (hh, hl, lh), 4-stage cp.async pipeline.
// 512 threads = 16 warps as 4(M) x 4(N); warp tile 64x32.
// ---------------------------------------------------------------------------
__global__ __launch_bounds__(512, 1) void gemm_mma(float* __restrict__ C) {
    extern __shared__ char smem[];
    const uint32_t sb = smem_u32(smem);
    const int tid = threadIdx.x;
    const int wid = tid >> 5, lane = tid & 31;
    const int b = blockIdx.z;
    const int bm = blockIdx.y * BM, bn = blockIdx.x * BN;

    const size_t boffA = (size_t)b * MDIM * KDIM;
    const size_t boffB = (size_t)b * KDIM * NDIM;
    const __nv_bfloat16* pAh = g_Ah + boffA;
    const __nv_bfloat16* pAl = g_Al + boffA;
    const __nv_bfloat16* pBh = g_Bh + boffB;
    const __nv_bfloat16* pBl = g_Bl + boffB;

    // cp.async geometry (512 threads)
    const int ar = tid >> 2, ac = tid & 3;       // A: rows ar, ar+128; chunk ac
    const int bk = tid >> 4, bc = tid & 15;      // B: row bk; chunk bc
    const uint32_t saw = (uint32_t)(ar * 4 + (ac ^ ((ar >> 1) & 3))) * 16;  // +8192 for row+128
    const uint32_t sbw = (uint32_t)(bk * 16 + (bc ^ (bk & 7))) * 16;

    const __nv_bfloat16* gAh0 = pAh + (size_t)(bm + ar) * KDIM + ac * 8;
    const __nv_bfloat16* gAl0 = pAl + (size_t)(bm + ar) * KDIM + ac * 8;
    const __nv_bfloat16* gBh0 = pBh + (size_t)bk * NDIM + bn + bc * 8;
    const __nv_bfloat16* gBl0 = pBl + (size_t)bk * NDIM + bn + bc * 8;

    auto load_stage = [&](int t) {
        const uint32_t st = sb + (uint32_t)(t % STAGES) * STAGE_BYTES;
        const size_t aoff = (size_t)(t * BK);
        const size_t boff = (size_t)(t * BK) * NDIM;
        cpa16(st + saw,                     gAh0 + aoff);
        cpa16(st + saw + 8192,              gAh0 + aoff + (size_t)128 * KDIM);
        cpa16(st + A_ST_BYTES + saw,        gAl0 + aoff);
        cpa16(st + A_ST_BYTES + saw + 8192, gAl0 + aoff + (size_t)128 * KDIM);
        const uint32_t sB = st + 2 * A_ST_BYTES;
        cpa16(sB + sbw,                     gBh0 + boff);
        cpa16(sB + B_ST_BYTES + sbw,        gBl0 + boff);
    };

    // warp tiling: 4(M) x 4(N)
    const int wm = (wid >> 2) * 64;      // 0,64,128,192
    const int wn = (wid & 3) * 32;       // 0,32,64,96

    // ldmatrix lane geometry
    const int a_r = wm + (lane & 15);            // + i*16
    const int a_cL = (lane >> 4);                // + ks*2
    const int b_k = (lane & 15);                 // + ks*16
    const int b_cL = (wn >> 3) + (lane >> 4);    // + j2*2

    float acc[4][4][4];
#pragma unroll
    for (int i = 0; i < 4; i++)
#pragma unroll
        for (int j = 0; j < 4; j++)
#pragma unroll
            for (int q = 0; q < 4; q++) acc[i][j][q] = 0.0f;

    // prologue
#pragma unroll
    for (int t = 0; t < STAGES - 1; ++t) {
        load_stage(t);
        asm volatile("cp.async.commit_group;" ::: "memory");
    }

    for (int t = 0; t < NK; ++t) {
        asm volatile("cp.async.wait_group %0;" :: "n"(STAGES - 2) : "memory");
        __syncthreads();

        if (t + STAGES - 1 < NK) load_stage(t + STAGES - 1);
        asm volatile("cp.async.commit_group;" ::: "memory");

        const uint32_t st = sb + (uint32_t)(t % STAGES) * STAGE_BYTES;
        const uint32_t sAh = st;
        const uint32_t sAl = st + A_ST_BYTES;
        const uint32_t sBh = st + 2 * A_ST_BYTES;
        const uint32_t sBl = sBh + B_ST_BYTES;

#pragma unroll
        for (int ks = 0; ks < 2; ks++) {
            uint32_t ah[4][4], al[4][4], bh[2][4], bl[2][4];
#pragma unroll
            for (int i = 0; i < 4; i++) {
                const int r = a_r + i * 16;
                const int c = ks * 2 + a_cL;
                const uint32_t off = (uint32_t)(r * 4 + (c ^ ((r >> 1) & 3))) * 16;
                ldsm_x4(ah[i], sAh + off);
                ldsm_x4(al[i], sAl + off);
            }
#pragma unroll
            for (int j2 = 0; j2 < 2; j2++) {
                const int k = ks * 16 + b_k;
                const int c = b_cL + j2 * 2;
                const uint32_t off = (uint32_t)(k * 16 + (c ^ (k & 7))) * 16;
                ldsm_x4_t(bh[j2], sBh + off);
                ldsm_x4_t(bl[j2], sBl + off);
            }
#pragma unroll
            for (int i = 0; i < 4; i++)
#pragma unroll
                for (int j2 = 0; j2 < 2; j2++)
#pragma unroll
                    for (int n8 = 0; n8 < 2; n8++) {
                        float* a4 = acc[i][j2 * 2 + n8];
                        mma_bf16(a4, ah[i], &bh[j2][n8 * 2]);
                        mma_bf16(a4, ah[i], &bl[j2][n8 * 2]);
                        mma_bf16(a4, al[i], &bh[j2][n8 * 2]);
                    }
        }
        // no trailing barrier: the next iteration's top-of-loop __syncthreads
        // orders all warps' compute(t) before anyone overwrites stage t
        // (write target at iter t+1 is stage (t+4)%4 == t%4).
    }

    // epilogue
    float* Cb = C + (size_t)b * MDIM * NDIM;
    const int r0 = bm + wm + (lane >> 2);
    const int c0 = bn + wn + (lane & 3) * 2;
#pragma unroll
    for (int i = 0; i < 4; i++) {
#pragma unroll
        for (int j = 0; j < 4; j++) {
            const int row = r0 + i * 16;
            const int col = c0 + j * 8;
            *(float2*)&Cb[(size_t)row * NDIM + col] = make_float2(acc[i][j][0], acc[i][j][1]);
            *(float2*)&Cb[(size_t)(row + 8) * NDIM + col] = make_float2(acc[i][j][2], acc[i][j][3]);
        }
    }
}

extern "C" void kernel_launch(void* const* d_in, const int* in_sizes, int n_in,
                              void* d_out, int out_size) {
    const float* a = (const float*)d_in[0];
    const float* b = (const float*)d_in[1];
    float* out = (float*)d_out;

    __nv_bfloat16 *Ah, *Al, *Bh, *Bl;
    cudaGetSymbolAddress((void**)&Ah, g_Ah);
    cudaGetSymbolAddress((void**)&Al, g_Al);
    cudaGetSymbolAddress((void**)&Bh, g_Bh);
    cudaGetSymbolAddress((void**)&Bl, g_Bl);

    dim3 pre_grid(NTILES, NTILES, BATCH);
    prescan_kernel<<<pre_grid, 256>>>(a);

    const int conv_blocks = (BATCH * MDIM * KDIM / 4) / 256;   // 32768
    conv_kernel<true><<<conv_blocks, 256>>>(a, Ah, Al);
    conv_kernel<false><<<conv_blocks, 256>>>(b, Bh, Bl);

    cudaFuncSetAttribute(gemm_mma, cudaFuncAttributeMaxDynamicSharedMemorySize, SMEM_TOTAL);
    dim3 grid(NDIM / BN, MDIM / BM, BATCH);
    gemm_mma<<<grid, 512, SMEM_TOTAL>>>(out);
}